// round 2
// baseline (speedup 1.0000x reference)
#include <cuda_runtime.h>

#define NN   50000
#define NNZB 800000
#define FIN  128
#define FOUT 64

// Scratch (allocation-free rule: __device__ globals)
__device__ __align__(16) float g_h[NN * FOUT];          // 12.8 MB
__device__ __align__(16) float g_y[3 * NN * FOUT];      // 38.4 MB (blocks 1..3 only; y[0] is dead)

__device__ __forceinline__ void red4(float* addr, float4 v) {
    asm volatile("red.global.add.v4.f32 [%0], {%1,%2,%3,%4};"
                 :: "l"(addr), "f"(v.x), "f"(v.y), "f"(v.z), "f"(v.w)
                 : "memory");
}

// Zero g_y, seed out with bias (d_out arrives poisoned).
__global__ void init_kernel(const float* __restrict__ bias, float* __restrict__ out) {
    int idx = blockIdx.x * blockDim.x + threadIdx.x;   // float4 index
    const int ytot = 3 * NN * FOUT / 4;
    const int otot = NN * FOUT / 4;
    if (idx < ytot) ((float4*)g_y)[idx] = make_float4(0.f, 0.f, 0.f, 0.f);
    if (idx < otot) {
        int f = (idx & 15) * 4;   // FOUT/4 = 16 float4 per row
        ((float4*)out)[idx] = make_float4(bias[f], bias[f + 1], bias[f + 2], bias[f + 3]);
    }
}

// h = x @ W.  W (128x64 fp32 = 32KB) staged in smem once per block.
// Block = 64 rows, 256 threads; thread -> (row = t/4, 16 cols starting at (t%4)*16).
__global__ void gemm_kernel(const float* __restrict__ x, const float* __restrict__ w) {
    __shared__ float ws[FIN * FOUT];
    for (int i = threadIdx.x; i < FIN * FOUT / 4; i += blockDim.x)
        ((float4*)ws)[i] = ((const float4*)w)[i];
    __syncthreads();

    int row = blockIdx.x * 64 + (threadIdx.x >> 2);
    if (row >= NN) return;
    int cb = (threadIdx.x & 3) * 16;

    float acc[16];
    #pragma unroll
    for (int j = 0; j < 16; j++) acc[j] = 0.f;

    const float4* xr = (const float4*)(x + (size_t)row * FIN);
    #pragma unroll
    for (int k4 = 0; k4 < FIN / 4; k4++) {
        float4 xv = __ldg(xr + k4);
        #pragma unroll
        for (int kk = 0; kk < 4; kk++) {
            float xs = (&xv.x)[kk];
            const float* wr = ws + (k4 * 4 + kk) * FOUT + cb;
            #pragma unroll
            for (int j = 0; j < 16; j++) acc[j] = fmaf(xs, wr[j], acc[j]);
        }
    }
    float* hr = g_h + (size_t)row * FOUT + cb;
    #pragma unroll
    for (int j = 0; j < 16; j += 4)
        *(float4*)(hr + j) = make_float4(acc[j], acc[j + 1], acc[j + 2], acc[j + 3]);
}

// Pass 1: y[b-1][r] += filt[b*N + r] * v * h[c], b in {1,2,3} (filt fused into scatter).
// 16 lanes per nnz, one float4 of the 64 features per lane.
__global__ void spmm1_kernel(const float* __restrict__ vals,
                             const int*   __restrict__ rows,
                             const int*   __restrict__ cols,
                             const float* __restrict__ filt) {
    int b = blockIdx.y + 1;
    int t = blockIdx.x * blockDim.x + threadIdx.x;
    int lane = t & 15;
    int i    = t >> 4;
    size_t e = (size_t)b * NNZB + i;
    int r = __ldg(rows + e);
    int c = __ldg(cols + e);
    float v = __ldg(vals + e) * __ldg(filt + (size_t)b * NN + r);
    float4 hv = __ldg((const float4*)(g_h + (size_t)c * FOUT) + lane);
    red4(g_y + ((size_t)(b - 1) * NN + r) * FOUT + lane * 4,
         make_float4(v * hv.x, v * hv.y, v * hv.z, v * hv.w));
}

// Pass 2: out[r] += v * y[b-1][c], b in {1,2,3}.
__global__ void spmm2_kernel(const float* __restrict__ vals,
                             const int*   __restrict__ rows,
                             const int*   __restrict__ cols,
                             float*       __restrict__ out) {
    int b = blockIdx.y + 1;
    int t = blockIdx.x * blockDim.x + threadIdx.x;
    int lane = t & 15;
    int i    = t >> 4;
    size_t e = (size_t)b * NNZB + i;
    int r = __ldg(rows + e);
    int c = __ldg(cols + e);
    float v = __ldg(vals + e);
    float4 yv = __ldg((const float4*)(g_y + ((size_t)(b - 1) * NN + c) * FOUT) + lane);
    red4(out + (size_t)r * FOUT + lane * 4,
         make_float4(v * yv.x, v * yv.y, v * yv.z, v * yv.w));
}

extern "C" void kernel_launch(void* const* d_in, const int* in_sizes, int n_in,
                              void* d_out, int out_size) {
    const float* x    = (const float*)d_in[0];   // [N, 128]
    const float* w    = (const float*)d_in[1];   // [128, 64]
    const float* filt = (const float*)d_in[2];   // [4*N]
    const float* bias = (const float*)d_in[3];   // [64]
    const float* vals = (const float*)d_in[4];   // [4, NNZ]
    const int*   rows = (const int*)  d_in[5];   // [4, NNZ]
    const int*   cols = (const int*)  d_in[6];   // [4, NNZ]
    float* out = (float*)d_out;                  // [N, 64]

    // init: cover 3*N*64/4 = 2.4M float4 -> 9375 blocks of 256
    init_kernel<<<(3 * NN * FOUT / 4 + 255) / 256, 256>>>(bias, out);
    gemm_kernel<<<(NN + 63) / 64, 256>>>(x, w);
    // NNZ * 16 lanes / 256 threads = exactly 50000 blocks per block-slice
    spmm1_kernel<<<dim3(NNZB * 16 / 256, 3), 256>>>(vals, rows, cols, filt);
    spmm2_kernel<<<dim3(NNZB * 16 / 256, 3), 256>>>(vals, rows, cols, out);
}

// round 6
// speedup vs baseline: 1.0393x; 1.0393x over previous
#include <cuda_runtime.h>

#define NN   50000
#define NNZB 800000
#define FIN  128
#define FOUT 64

__device__ __align__(16) float g_h[NN * FOUT];          // 12.8 MB
__device__ __align__(16) float g_y[3 * NN * FOUT];      // 38.4 MB (blocks 1..3; block 0 dead)

__device__ __forceinline__ void red4(float* addr, float x, float y, float z, float w) {
    asm volatile("red.global.add.v4.f32 [%0], {%1,%2,%3,%4};"
                 :: "l"(addr), "f"(x), "f"(y), "f"(z), "f"(w)
                 : "memory");
}

// Zero g_y, seed out with bias (d_out arrives poisoned).
__global__ void init_kernel(const float* __restrict__ bias, float* __restrict__ out) {
    int idx = blockIdx.x * blockDim.x + threadIdx.x;   // float4 index
    const int ytot = 3 * NN * FOUT / 4;
    const int otot = NN * FOUT / 4;
    if (idx < ytot) ((float4*)g_y)[idx] = make_float4(0.f, 0.f, 0.f, 0.f);
    if (idx < otot) {
        int f = (idx & 15) * 4;   // 16 float4 per row
        ((float4*)out)[idx] = make_float4(bias[f], bias[f + 1], bias[f + 2], bias[f + 3]);
    }
}

// h = x @ W.  W (128x64 = 32KB) staged in smem.
__global__ void gemm_kernel(const float* __restrict__ x, const float* __restrict__ w) {
    __shared__ float ws[FIN * FOUT];
    for (int i = threadIdx.x; i < FIN * FOUT / 4; i += blockDim.x)
        ((float4*)ws)[i] = ((const float4*)w)[i];
    __syncthreads();

    int row = blockIdx.x * 64 + (threadIdx.x >> 2);
    if (row >= NN) return;
    int cb = (threadIdx.x & 3) * 16;

    float acc[16];
    #pragma unroll
    for (int j = 0; j < 16; j++) acc[j] = 0.f;

    const float4* xr = (const float4*)(x + (size_t)row * FIN);
    #pragma unroll
    for (int k4 = 0; k4 < FIN / 4; k4++) {
        float4 xv = __ldg(xr + k4);
        #pragma unroll
        for (int kk = 0; kk < 4; kk++) {
            float xs = (&xv.x)[kk];
            const float* wr = ws + (k4 * 4 + kk) * FOUT + cb;
            #pragma unroll
            for (int j = 0; j < 16; j++) acc[j] = fmaf(xs, wr[j], acc[j]);
        }
    }
    float* hr = g_h + (size_t)row * FOUT + cb;
    #pragma unroll
    for (int j = 0; j < 16; j += 4)
        *(float4*)(hr + j) = make_float4(acc[j], acc[j + 1], acc[j + 2], acc[j + 3]);
}

// ── SpMM mapping: 4 lanes per nnz, 8 nnz per warp, 64 nnz per 256-thread block.
//    Each thread: 4 independent float4 gathers (MLP=4) + 4 red.v4 scatters.

// Pass 1: y[b-1][r] += filt[b*N+r] * v * h[c],  b in {1,2,3}
__global__ void spmm1_kernel(const float* __restrict__ vals,
                             const int*   __restrict__ rows,
                             const int*   __restrict__ cols,
                             const float* __restrict__ filt) {
    const int b = blockIdx.y + 1;
    int lane = threadIdx.x & 31;
    int g = lane >> 2;             // nnz group within warp (0..7)
    int s = lane & 3;              // sublane: which 16B of the 64B chunk pattern
    int i = blockIdx.x * 64 + (threadIdx.x >> 5) * 8 + g;
    size_t e = (size_t)b * NNZB + i;

    int r = __ldg(rows + e);
    int c = __ldg(cols + e);
    float v = __ldg(vals + e) * __ldg(filt + (size_t)b * NN + r);

    const float4* hp = (const float4*)(g_h + (size_t)c * FOUT);
    float4 a0 = __ldg(hp + s);          // lanes of a group cover floats [0,16)
    float4 a1 = __ldg(hp + 4 + s);      // [16,32)
    float4 a2 = __ldg(hp + 8 + s);      // [32,48)
    float4 a3 = __ldg(hp + 12 + s);     // [48,64)

    float* yp = g_y + ((size_t)(b - 1) * NN + r) * FOUT;
    red4(yp + (s) * 4,      v * a0.x, v * a0.y, v * a0.z, v * a0.w);
    red4(yp + (4 + s) * 4,  v * a1.x, v * a1.y, v * a1.z, v * a1.w);
    red4(yp + (8 + s) * 4,  v * a2.x, v * a2.y, v * a2.z, v * a2.w);
    red4(yp + (12 + s) * 4, v * a3.x, v * a3.y, v * a3.z, v * a3.w);
}

// Pass 2: out[r] += v * y[b-1][c],  b in {1,2,3}
__global__ void spmm2_kernel(const float* __restrict__ vals,
                             const int*   __restrict__ rows,
                             const int*   __restrict__ cols,
                             float*       __restrict__ out) {
    const int b = blockIdx.y + 1;
    int lane = threadIdx.x & 31;
    int g = lane >> 2;
    int s = lane & 3;
    int i = blockIdx.x * 64 + (threadIdx.x >> 5) * 8 + g;
    size_t e = (size_t)b * NNZB + i;

    int r = __ldg(rows + e);
    int c = __ldg(cols + e);
    float v = __ldg(vals + e);

    const float4* yp = (const float4*)(g_y + ((size_t)(b - 1) * NN + c) * FOUT);
    float4 a0 = __ldg(yp + s);
    float4 a1 = __ldg(yp + 4 + s);
    float4 a2 = __ldg(yp + 8 + s);
    float4 a3 = __ldg(yp + 12 + s);

    float* op = out + (size_t)r * FOUT;
    red4(op + (s) * 4,      v * a0.x, v * a0.y, v * a0.z, v * a0.w);
    red4(op + (4 + s) * 4,  v * a1.x, v * a1.y, v * a1.z, v * a1.w);
    red4(op + (8 + s) * 4,  v * a2.x, v * a2.y, v * a2.z, v * a2.w);
    red4(op + (12 + s) * 4, v * a3.x, v * a3.y, v * a3.z, v * a3.w);
}

extern "C" void kernel_launch(void* const* d_in, const int* in_sizes, int n_in,
                              void* d_out, int out_size) {
    const float* x    = (const float*)d_in[0];   // [N, 128]
    const float* w    = (const float*)d_in[1];   // [128, 64]
    const float* filt = (const float*)d_in[2];   // [4*N]
    const float* bias = (const float*)d_in[3];   // [64]
    const float* vals = (const float*)d_in[4];   // [4, NNZ]
    const int*   rows = (const int*)  d_in[5];   // [4, NNZ]
    const int*   cols = (const int*)  d_in[6];   // [4, NNZ]
    float* out = (float*)d_out;                  // [N, 64]

    init_kernel<<<(3 * NN * FOUT / 4 + 255) / 256, 256>>>(bias, out);
    gemm_kernel<<<(NN + 63) / 64, 256>>>(x, w);
    // 64 nnz per block -> NNZB/64 = 12500 blocks per framelet block, 3 blocks
    spmm1_kernel<<<dim3(NNZB / 64, 3), 256>>>(vals, rows, cols, filt);
    spmm2_kernel<<<dim3(NNZB / 64, 3), 256>>>(vals, rows, cols, out);
}